// round 6
// baseline (speedup 1.0000x reference)
#include <cuda_runtime.h>

// Entropy_70136815944310 — R6: vertical sliding window + mod-4 bin split.
// FOUR threads per column share one 256-bin histogram: thread p owns bins
// b with b%4 == p. The 4 bins touched per value (i0-1..i0+2) are consecutive,
// so each thread does exactly ONE RMW (+1 log-pair) per value. 24 warps/SM.
// Quad partials (S, T2) combined via shfl_xor(1) + shfl_xor(2).
//
// x: [8,3,96,96] fp32 in [0,255]; out: same shape fp32.
// KDE kernel k(x,b) = e/(1+e)^2, e = exp(-10|x-b|): only bins
// floor(x)-1..floor(x)+2 matter (validated rel_err ~3.5e-7). With
// f = x-floor(x): E = exp(-10f); bins' e are gE, E, g/E, g2/E, g = exp(-10).
// Far bins: k = e(1-2e), err < 3e-13.
// H = (S*log(S') - T2)/S', S' = S + 1e-10, T2 = sum q*log q.

#define IMG      96
#define SEG      8                    // output rows per column-quad
#define NSEG     (IMG / SEG)          // 12
#define THREADS  (IMG * 4)            // 384: lanes 4c..4c+3 = column c
#define HSTRIDE  260                  // 256 + 4 pad
#define TROWS    (SEG + 4)            // 12
#define TCOLS    (IMG + 4)            // 100
#define NBINS    256
#define SMEM_BYTES ((IMG * HSTRIDE + TROWS * TCOLS) * 4)   // 104,640 B

__device__ __forceinline__ float frcp(float v) {
    float r; asm("rcp.approx.f32 %0, %1;" : "=f"(r) : "f"(v)); return r;
}
// q==0 -> 0*log(1e-37)==0 exactly; tiny negative rounding residue -> ~1e-9, negligible
__device__ __forceinline__ float qlogq(float q) {
    return q * __logf(fmaxf(q, 1e-37f));
}

// Owned bin + its kernel mass for thread parity p (bins b%4==p).
// Among i0-1..i0+2 exactly one matches: j = (p - (i0-1)) & 3, b = i0-1+j.
__device__ __forceinline__ void kde_own(float x, int p, int& b, float& k) {
    const float g  = 4.5399929762484854e-05f;   // exp(-10)
    const float g2 = 2.0611536224385578e-09f;   // exp(-20)
    float fl = floorf(x);
    int  i0  = (int)fl;
    float f  = x - fl;
    float E  = __expf(-10.f * f);
    float iE = frcp(E);
    float e1 = g * iE;
    float r0 = frcp(1.f + E);
    float r1 = frcp(1.f + e1);
    float k0 = E  * r0 * r0;           // bin i0
    float k1 = e1 * r1 * r1;           // bin i0+1
    float em = g * E;
    float km1 = em - 2.f * em * em;    // bin i0-1
    float e2 = g2 * iE;
    float k2  = e2 - 2.f * e2 * e2;    // bin i0+2
    int j = (p - i0 + 1) & 3;
    b = i0 - 1 + j;
    k = (j == 0) ? km1 : (j == 1) ? k0 : (j == 2) ? k1 : k2;
}

__global__ __launch_bounds__(THREADS, 2)
void entropy_kernel(const float* __restrict__ in, float* __restrict__ out) {
    extern __shared__ float smem[];
    float* tile = smem + IMG * HSTRIDE;

    const int tid   = threadIdx.x;
    const int col   = tid >> 2;                    // column 0..95
    const int par   = tid & 3;                     // owns bins b%4 == par
    const int plane = blockIdx.y;
    const int r0    = blockIdx.x * SEG;
    const float* img = in  + (size_t)plane * IMG * IMG;
    float*       o   = out + (size_t)plane * IMG * IMG;

    // ---- tile: rows r0-2..r0+SEG+1, cols -2..97; OOB sentinel -10
    // (its bins are negative -> rejected == SAME padding's additive identity) ----
    for (int idx = tid; idx < TROWS * TCOLS; idx += THREADS) {
        int r = idx / TCOLS, c = idx % TCOLS;
        int gy = r0 + r - 2, gx = c - 2;
        float v = -10.0f;
        if ((unsigned)gy < (unsigned)IMG && (unsigned)gx < (unsigned)IMG)
            v = img[gy * IMG + gx];
        tile[idx] = v;
    }

    // ---- zero own quarter of the column histogram (stride-4 scalar,
    // bank = (4col + 4i + par) % 32: all 32 banks distinct per warp step) ----
    float* h = smem + col * HSTRIDE;
    #pragma unroll 8
    for (int b = par; b < NBINS; b += 4)
        h[b] = 0.f;

    __syncthreads();

    // ---- build initial histogram for y = r0 (own bin per value) ----
    #pragma unroll 1
    for (int wr = 0; wr < 5; wr++) {
        const float* trow = tile + wr * TCOLS + col;
        #pragma unroll
        for (int wc = 0; wc < 5; wc++) {
            float v = trow[wc];
            if (v >= 0.f) {
                int b; float k;
                kde_own(v, par, b, k);
                if ((unsigned)b < (unsigned)NBINS) h[b] += k;
            }
        }
    }

    // ---- initial scan of owned bins: S, T2 (conflict-free scalar) ----
    float S = 0.f, T2 = 0.f;
    #pragma unroll 8
    for (int b = par; b < NBINS; b += 4) {
        float q = h[b];
        S  += q;
        T2 += qlogq(q);
    }

    {
        float St = S, Tt = T2;
        St += __shfl_xor_sync(0xffffffffu, St, 1);
        Tt += __shfl_xor_sync(0xffffffffu, Tt, 1);
        St += __shfl_xor_sync(0xffffffffu, St, 2);
        Tt += __shfl_xor_sync(0xffffffffu, Tt, 2);
        float Sp = St + 1e-10f;
        if (par == 0)
            o[r0 * IMG + col] = __fdividef(St * __logf(Sp) - Tt, Sp);
    }

    // ---- slide down: remove tile row step-1, add tile row step+4 ----
    #pragma unroll 1
    for (int step = 1; step < SEG; step++) {
        const float* rem = tile + (step - 1) * TCOLS + col;
        const float* add = tile + (step + 4) * TCOLS + col;

        float Sr = 0.f, Tr = 0.f;   // separate accumulators: shorter FADD chains
        #pragma unroll
        for (int wc = 0; wc < 5; wc++) {
            float v = rem[wc];
            if (v >= 0.f) {
                int b; float k;
                kde_own(v, par, b, k);
                if ((unsigned)b < (unsigned)NBINS) {
                    float q = h[b], qn = q - k;
                    h[b] = qn;
                    Tr += qlogq(qn) - qlogq(q);
                    Sr -= k;
                }
            }
        }
        #pragma unroll
        for (int wc = 0; wc < 5; wc++) {
            float v = add[wc];
            if (v >= 0.f) {
                int b; float k;
                kde_own(v, par, b, k);
                if ((unsigned)b < (unsigned)NBINS) {
                    float q = h[b], qn = q + k;
                    h[b] = qn;
                    Tr += qlogq(qn) - qlogq(q);
                    Sr += k;
                }
            }
        }
        S  += Sr;
        T2 += Tr;

        float St = S, Tt = T2;
        St += __shfl_xor_sync(0xffffffffu, St, 1);
        Tt += __shfl_xor_sync(0xffffffffu, Tt, 1);
        St += __shfl_xor_sync(0xffffffffu, St, 2);
        Tt += __shfl_xor_sync(0xffffffffu, Tt, 2);
        float Sp = St + 1e-10f;
        if (par == 0)
            o[(r0 + step) * IMG + col] = __fdividef(St * __logf(Sp) - Tt, Sp);
    }
}

extern "C" void kernel_launch(void* const* d_in, const int* in_sizes, int n_in,
                              void* d_out, int out_size) {
    const float* x = (const float*)d_in[0];
    float* out = (float*)d_out;

    cudaFuncSetAttribute(entropy_kernel,
                         cudaFuncAttributeMaxDynamicSharedMemorySize, SMEM_BYTES);

    int planes = in_sizes[0] / (IMG * IMG);   // 24
    dim3 grid(NSEG, planes);                  // (12, 24) = 288 CTAs
    entropy_kernel<<<grid, THREADS, SMEM_BYTES>>>(x, out);
}

// round 7
// speedup vs baseline: 1.1892x; 1.1892x over previous
#include <cuda_runtime.h>

// Entropy_70136815944310 — R7: R5 (pair parity-split sliding window, best
// known 33.2us) + 3-bin KDE truncation + parity-aware kernel eval.
//
// x: [8,3,96,96] fp32 in [0,255]; out: same shape fp32.
//
// KDE kernel k(x,b) = e/(1+e)^2, e = exp(-10|x-b|). Bins i0 and i0+1
// (i0 = floor(x), f = x-i0) dominate; of the far bins {i0-1, i0+2} the
// smaller has mass <= exp(-15) = 3.1e-7 -> keep only the larger
// (i0-1 if f<0.5 else i0+2). Entropy error < 1e-5 rel.
//   near e's: E = exp(-10f) for bin i0, g/E for bin i0+1 (g = exp(-10))
//   far  e:   g*E (f<0.5) or g2/E (f>=0.5), k_far = e(1-2e), err < 3e-13.
//
// Two threads per column share one 256-bin histogram; thread parity p owns
// bins with (b&1)==p. Near bins i0, i0+1 have opposite parity -> exactly one
// per thread. Far bin parity == (f<0.5 ? !pn : pn) -> exactly one lane of the
// pair. S = sum q, T2 = sum q*log q maintained incrementally;
// H = (S*log(S') - T2)/S', S' = S + 1e-10. Pair combine via shfl_xor(1).

#define IMG      96
#define SEG      8                    // output rows per thread pair
#define NSEG     (IMG / SEG)          // 12
#define THREADS  (IMG * 2)            // 192: lanes (2c, 2c+1) = column c
#define HSTRIDE  260                  // 256 + 4 pad
#define TROWS    (SEG + 4)            // 12
#define TCOLS    (IMG + 4)            // 100
#define NBINS    256
#define SMEM_BYTES ((IMG * HSTRIDE + TROWS * TCOLS) * 4)   // 104,640 B

#define G1  4.5399929762484854e-05f   // exp(-10)
#define G2  2.0611536224385578e-09f   // exp(-20)

__device__ __forceinline__ float frcp(float v) {
    float r; asm("rcp.approx.f32 %0, %1;" : "=f"(r) : "f"(v)); return r;
}
// q==0 -> 0*log(1e-37)==0 exactly; tiny negative residue -> ~1e-9, negligible
__device__ __forceinline__ float qlogq(float q) {
    return q * __logf(fmaxf(q, 1e-37f));
}

// This thread's (up to 2) bin updates for value x, parity par.
// bn/kn: near bin (always valid, in [0,255]). bf/kf: far bin, valid iff
// this lane owns it AND it's in range; signalled by bf in [0,256) else bf=-1.
__device__ __forceinline__ void kde_pair(float x, int par,
                                         int& bn, float& kn, int& bf, float& kf) {
    float fl = floorf(x);
    int   i0 = (int)fl;                 // [0, 254]
    float f  = x - fl;
    float E  = __expf(-10.f * f);
    float iE = frcp(E);
    bool  pn = ((i0 & 1) == par);       // own the i0 bin?
    // near bin: e = E (bin i0) or g/E (bin i0+1)
    float en = pn ? E : (G1 * iE);
    float rn = frcp(1.f + en);
    bn = i0 + (pn ? 0 : 1);
    kn = en * rn * rn;
    // far bin: i0-1 (f<0.5) or i0+2; owned by lane (lo ? !pn : pn)
    bool lo = (f < 0.5f);
    bool own_far = lo ? !pn : pn;
    if (own_far) {
        float ef = lo ? (G1 * E) : (G2 * iE);
        kf = ef - 2.f * ef * ef;
        int b = lo ? (i0 - 1) : (i0 + 2);
        bf = ((unsigned)b < (unsigned)NBINS) ? b : -1;
    } else {
        bf = -1; kf = 0.f;
    }
}

__global__ __launch_bounds__(THREADS, 2)
void entropy_kernel(const float* __restrict__ in, float* __restrict__ out) {
    extern __shared__ float smem[];
    float* tile = smem + IMG * HSTRIDE;

    const int tid   = threadIdx.x;
    const int col   = tid >> 1;                    // column 0..95
    const int par   = tid & 1;                     // owns bins (b&1)==par
    const int plane = blockIdx.y;
    const int r0    = blockIdx.x * SEG;
    const float* img = in  + (size_t)plane * IMG * IMG;
    float*       o   = out + (size_t)plane * IMG * IMG;

    // ---- tile: rows r0-2..r0+SEG+1, cols -2..97; OOB sentinel -10
    // (negative bins -> rejected == SAME padding's additive identity) ----
    for (int idx = tid; idx < TROWS * TCOLS; idx += THREADS) {
        int r = idx / TCOLS, c = idx % TCOLS;
        int gy = r0 + r - 2, gx = c - 2;
        float v = -10.0f;
        if ((unsigned)gy < (unsigned)IMG && (unsigned)gx < (unsigned)IMG)
            v = img[gy * IMG + gx];
        tile[idx] = v;
    }

    // ---- zero own half of the histogram (interleaved float4 quads) ----
    float* h  = smem + col * HSTRIDE;
    float4* h4 = (float4*)h;
    #pragma unroll 8
    for (int i = par; i < NBINS / 4; i += 2)
        h4[i] = make_float4(0.f, 0.f, 0.f, 0.f);

    __syncthreads();

    // ---- build initial histogram for y = r0 ----
    #pragma unroll 1
    for (int wr = 0; wr < 5; wr++) {
        const float* trow = tile + wr * TCOLS + col;
        #pragma unroll
        for (int wc = 0; wc < 5; wc++) {
            float v = trow[wc];
            if (v >= 0.f) {
                int bn, bf; float kn, kf;
                kde_pair(v, par, bn, kn, bf, kf);
                h[bn] += kn;
                if (bf >= 0) h[bf] += kf;
            }
        }
    }

    // ---- initial scan of owned quads: S, T2 ----
    float S = 0.f, T2 = 0.f;
    #pragma unroll 4
    for (int i = par; i < NBINS / 4; i += 2) {
        float4 q = h4[i];
        S  += (q.x + q.y) + (q.z + q.w);
        T2 += qlogq(q.x) + qlogq(q.y) + qlogq(q.z) + qlogq(q.w);
    }

    {
        float St = S  + __shfl_xor_sync(0xffffffffu, S,  1);
        float Tt = T2 + __shfl_xor_sync(0xffffffffu, T2, 1);
        float Sp = St + 1e-10f;
        if (par == 0)
            o[r0 * IMG + col] = __fdividef(St * __logf(Sp) - Tt, Sp);
    }

    // ---- slide down: remove tile row step-1, add tile row step+4 ----
    #pragma unroll 1
    for (int step = 1; step < SEG; step++) {
        const float* rem = tile + (step - 1) * TCOLS + col;
        const float* add = tile + (step + 4) * TCOLS + col;

        float Sr = 0.f, Tr = 0.f;     // local accumulators: short FADD chains
        #pragma unroll
        for (int wc = 0; wc < 5; wc++) {
            float v = rem[wc];
            if (v >= 0.f) {
                int bn, bf; float kn, kf;
                kde_pair(v, par, bn, kn, bf, kf);
                {
                    float q = h[bn], qn = q - kn;
                    h[bn] = qn;
                    Tr += qlogq(qn) - qlogq(q);
                    Sr -= kn;
                }
                if (bf >= 0) {
                    float q = h[bf], qn = q - kf;
                    h[bf] = qn;
                    Tr += qlogq(qn) - qlogq(q);
                    Sr -= kf;
                }
            }
        }
        #pragma unroll
        for (int wc = 0; wc < 5; wc++) {
            float v = add[wc];
            if (v >= 0.f) {
                int bn, bf; float kn, kf;
                kde_pair(v, par, bn, kn, bf, kf);
                {
                    float q = h[bn], qn = q + kn;
                    h[bn] = qn;
                    Tr += qlogq(qn) - qlogq(q);
                    Sr += kn;
                }
                if (bf >= 0) {
                    float q = h[bf], qn = q + kf;
                    h[bf] = qn;
                    Tr += qlogq(qn) - qlogq(q);
                    Sr += kf;
                }
            }
        }
        S  += Sr;
        T2 += Tr;

        float St = S  + __shfl_xor_sync(0xffffffffu, S,  1);
        float Tt = T2 + __shfl_xor_sync(0xffffffffu, T2, 1);
        float Sp = St + 1e-10f;
        if (par == 0)
            o[(r0 + step) * IMG + col] = __fdividef(St * __logf(Sp) - Tt, Sp);
    }
}

extern "C" void kernel_launch(void* const* d_in, const int* in_sizes, int n_in,
                              void* d_out, int out_size) {
    const float* x = (const float*)d_in[0];
    float* out = (float*)d_out;

    cudaFuncSetAttribute(entropy_kernel,
                         cudaFuncAttributeMaxDynamicSharedMemorySize, SMEM_BYTES);

    int planes = in_sizes[0] / (IMG * IMG);   // 24
    dim3 grid(NSEG, planes);                  // (12, 24) = 288 CTAs
    entropy_kernel<<<grid, THREADS, SMEM_BYTES>>>(x, out);
}